// round 2
// baseline (speedup 1.0000x reference)
#include <cuda_runtime.h>
#include <cstdint>

#define NN   102400
#define BB   256
#define LL   400
#define EE   819200
#define PADL 512

static const size_t OFF_SEQCNN = 0;
static const size_t OFF_GRAPH  = 16777216;
static const size_t OFF_MASK1  = 33554432;
static const size_t OFF_MASK2  = 33685504;
static const size_t OFF_EMBSEQ = 33816576;
static const size_t OFF_EMBGR  = 33849344;

// ---------------- scratch (device globals: no allocation allowed) ----------------
__device__ float g_h1[NN*256];
__device__ float g_hpre2[104857600];      // N x 1024
__device__ float g_h2[NN*256];
__device__ float g_hpre3[NN*128];
__device__ float g_h3[NN*128];
__device__ float g_emb2[NN*128];
__device__ float g_outr[BB*PADL*128];
__device__ float g_y[BB*PADL*64];
__device__ float g_t1[67108864];          // (B*512) x 512
__device__ float g_asn1[NN*4], g_adn1[NN*4];
__device__ float g_asn2[NN*4], g_adn2[NN*4];
__device__ float g_asn3[NN],   g_adn3[NN];
__device__ float g_tabh1[6*1024], g_tabas1[24], g_tabad1[24];
__device__ float g_weff[128*15*64], g_beff[64];
__device__ int g_cnt[NN], g_incl[NN], g_bsum[128], g_off[NN+1], g_cur[NN], g_csr[EE];

// ---------------- small table kernels ----------------
__global__ void k_tab_h1(const float* __restrict__ tabg, const float* __restrict__ W1){
    int idx = blockIdx.x*256 + threadIdx.x;           // < 6144
    int v = idx >> 10, col = idx & 1023;
    float s = 0.f;
    for (int k = 0; k < 128; k++) s += tabg[v*128+k] * W1[k*1024+col];
    g_tabh1[idx] = s;
}

__global__ void k_tab_attn(const float* __restrict__ a1s, const float* __restrict__ a1d){
    int w = threadIdx.x >> 5, lane = threadIdx.x & 31;
    if (w >= 24) return;
    int v = w >> 2, h = w & 3;
    float s = 0.f, d = 0.f;
    for (int c = lane; c < 256; c += 32){
        float hv = g_tabh1[v*1024 + h*256 + c];
        s += hv * a1s[h*256+c];
        d += hv * a1d[h*256+c];
    }
    for (int o = 16; o > 0; o >>= 1){
        s += __shfl_xor_sync(0xffffffffu, s, o);
        d += __shfl_xor_sync(0xffffffffu, d, o);
    }
    if (lane == 0){ g_tabas1[v*4+h] = s; g_tabad1[v*4+h] = d; }
}

__global__ void k_asn1(const int* __restrict__ x){
    int i = blockIdx.x*256 + threadIdx.x;
    if (i >= NN*4) return;
    int node = i >> 2, h = i & 3;
    int xi = x[node];
    g_asn1[i] = g_tabas1[xi*4+h];
    g_adn1[i] = g_tabad1[xi*4+h];
}

__global__ void k_weff(const float* __restrict__ cw1, const float* __restrict__ cb1,
                       const float* __restrict__ cw2, const float* __restrict__ cb2,
                       const float* __restrict__ cw3, const float* __restrict__ cb3){
    int idx = blockIdx.x*256 + threadIdx.x;
    if (idx >= 128*15*64) return;
    int ic = idx / 960, rem = idx % 960, j = rem / 64, oc = rem % 64;
    float v = cw3[(oc*128+ic)*15 + j];
    if (j >= 2 && j < 13) v += cw2[(oc*128+ic)*11 + (j-2)];
    if (j >= 4 && j < 11) v += cw1[(oc*128+ic)*7  + (j-4)];
    g_weff[idx] = v * (1.f/3.f);
    if (idx < 64) g_beff[idx] = (cb1[idx] + cb2[idx] + cb3[idx]) * (1.f/3.f);
}

// ---------------- CSR build ----------------
__global__ void k_count(const int* __restrict__ dst){
    int e = blockIdx.x*256 + threadIdx.x;
    if (e < EE) atomicAdd(&g_cnt[dst[e]], 1);
}
__global__ void k_scan1(){
    __shared__ int sh[1024];
    int tid = threadIdx.x;
    int i = blockIdx.x*1024 + tid;
    sh[tid] = g_cnt[i];
    __syncthreads();
    for (int ofs = 1; ofs < 1024; ofs <<= 1){
        int t = (tid >= ofs) ? sh[tid-ofs] : 0;
        __syncthreads();
        sh[tid] += t;
        __syncthreads();
    }
    g_incl[i] = sh[tid];
    if (tid == 1023) g_bsum[blockIdx.x] = sh[1023];
}
__global__ void k_scan2(){
    if (threadIdx.x == 0){
        int acc = 0;
        for (int i = 0; i < 100; i++){ int v = g_bsum[i]; g_bsum[i] = acc; acc += v; }
    }
}
__global__ void k_scan3(){
    int i = blockIdx.x*1024 + threadIdx.x;
    int ex = g_incl[i] - g_cnt[i] + g_bsum[blockIdx.x];
    g_off[i] = ex;
    g_cur[i] = ex;
    if (i == 0) g_off[NN] = EE;
}
__global__ void k_fill(const int* __restrict__ src, const int* __restrict__ dst){
    int e = blockIdx.x*256 + threadIdx.x;
    if (e >= EE) return;
    int d = dst[e];
    int p = atomicAdd(&g_cur[d], 1);
    g_csr[p] = src[e];
}

// ---------------- GAT aggregation: one warp per destination node ----------------
template<int H, int CH>
__global__ void k_gat_agg(const float* __restrict__ hmat, const int* __restrict__ remap,
                          const float* __restrict__ asn, const float* __restrict__ adn,
                          const float* __restrict__ bias, float* __restrict__ outp,
                          const int* __restrict__ off, const int* __restrict__ csr){
    const int P = CH/32;
    __shared__ int   s_src[8][128];
    __shared__ float s_al[8][128*H];
    int w = threadIdx.x >> 5, lane = threadIdx.x & 31;
    int node = blockIdx.x*8 + w;
    if (node >= NN) return;

    float ad[H], m[H], den[H], eself[H];
    #pragma unroll
    for (int h = 0; h < H; h++) ad[h] = adn[node*H+h];
    #pragma unroll
    for (int h = 0; h < H; h++){
        float v = asn[node*H+h] + ad[h];
        eself[h] = (v > 0.f) ? v : 0.2f*v;
        m[h] = eself[h];
    }
    int s0 = off[node], s1 = off[node+1];

    // pass 1: max
    for (int e = s0 + lane; e < s1; e += 32){
        int s = csr[e];
        #pragma unroll
        for (int h = 0; h < H; h++){
            float v = asn[s*H+h] + ad[h];
            v = (v > 0.f) ? v : 0.2f*v;
            m[h] = fmaxf(m[h], v);
        }
    }
    #pragma unroll
    for (int h = 0; h < H; h++)
        for (int o = 16; o > 0; o >>= 1) m[h] = fmaxf(m[h], __shfl_xor_sync(0xffffffffu, m[h], o));

    // pass 2: denom
    #pragma unroll
    for (int h = 0; h < H; h++) den[h] = 0.f;
    for (int e = s0 + lane; e < s1; e += 32){
        int s = csr[e];
        #pragma unroll
        for (int h = 0; h < H; h++){
            float v = asn[s*H+h] + ad[h];
            v = (v > 0.f) ? v : 0.2f*v;
            den[h] += __expf(v - m[h]);
        }
    }
    #pragma unroll
    for (int h = 0; h < H; h++){
        for (int o = 16; o > 0; o >>= 1) den[h] += __shfl_xor_sync(0xffffffffu, den[h], o);
        den[h] += __expf(eself[h] - m[h]);
    }
    float rden[H];
    #pragma unroll
    for (int h = 0; h < H; h++) rden[h] = 1.f / den[h];

    float acc[H][P];
    #pragma unroll
    for (int h = 0; h < H; h++)
        #pragma unroll
        for (int p = 0; p < P; p++) acc[h][p] = 0.f;

    // self loop
    {
        int row = remap ? remap[node] : node;
        const float* hp = hmat + (size_t)row*(H*CH);
        #pragma unroll
        for (int h = 0; h < H; h++){
            float a = __expf(eself[h] - m[h]) * rden[h];
            #pragma unroll
            for (int p = 0; p < P; p++) acc[h][p] += a * hp[h*CH + p*32 + lane];
        }
    }

    // pass 3: chunked weighted accumulate
    for (int base = s0; base < s1; base += 128){
        int cn = min(128, s1 - base);
        for (int e = lane; e < cn; e += 32){
            int s = csr[base + e];
            #pragma unroll
            for (int h = 0; h < H; h++){
                float v = asn[s*H+h] + ad[h];
                v = (v > 0.f) ? v : 0.2f*v;
                s_al[w][e*H+h] = __expf(v - m[h]) * rden[h];
            }
            s_src[w][e] = remap ? remap[s] : s;
        }
        __syncwarp();
        for (int e = 0; e < cn; e++){
            int row = s_src[w][e];
            const float* hp = hmat + (size_t)row*(H*CH);
            #pragma unroll
            for (int h = 0; h < H; h++){
                float a = s_al[w][e*H+h];
                #pragma unroll
                for (int p = 0; p < P; p++) acc[h][p] += a * hp[h*CH + p*32 + lane];
            }
        }
        __syncwarp();
    }

    const float invH = 1.f / (float)H;
    #pragma unroll
    for (int p = 0; p < P; p++){
        float v = 0.f;
        #pragma unroll
        for (int h = 0; h < H; h++) v += acc[h][p];
        v = v*invH + bias[p*32 + lane];
        outp[(size_t)node*CH + p*32 + lane] = (v > 0.f) ? v : 0.f;
    }
}

// ---------------- per-node attention dots (layers 2,3) ----------------
template<int H, int CH>
__global__ void k_dots(const float* __restrict__ hpre, const float* __restrict__ aw_s,
                       const float* __restrict__ aw_d, float* __restrict__ asn, float* __restrict__ adn){
    int gw = blockIdx.x*8 + (threadIdx.x >> 5);
    int lane = threadIdx.x & 31;
    if (gw >= NN*H) return;
    int node = gw / H, h = gw - node*H;
    const float* hp = hpre + (size_t)node*(H*CH) + h*CH;
    float s = 0.f, d = 0.f;
    for (int c = lane; c < CH; c += 32){
        float v = hp[c];
        s += v * aw_s[h*CH+c];
        d += v * aw_d[h*CH+c];
    }
    for (int o = 16; o > 0; o >>= 1){
        s += __shfl_xor_sync(0xffffffffu, s, o);
        d += __shfl_xor_sync(0xffffffffu, d, o);
    }
    if (lane == 0){ asn[gw] = s; adn[gw] = d; }
}

// ---------------- SGEMM: C = A(MxK) * B(KxN) [+bias][relu], tiles 128x128x16 ----------------
template<bool BIAS, bool RELU>
__global__ void __launch_bounds__(256) k_sgemm(const float* __restrict__ A, const float* __restrict__ B,
                                               const float* __restrict__ bias, float* __restrict__ C,
                                               int M, int Nn, int K){
    __shared__ float As[16][128];
    __shared__ float Bs[16][128];
    int tid = threadIdx.x;
    int bm = blockIdx.y, bn = blockIdx.x;
    int ty = tid >> 4, tx = tid & 15;
    int arow = tid >> 1, aq = (tid & 1) * 8;
    int brow = tid >> 5, bcol = (tid & 31) * 4;
    const float* Ap = A + (size_t)(bm*128 + arow)*K + aq;
    const float* Bp = B + (size_t)brow*Nn + bn*128 + bcol;
    float acc[8][8];
    #pragma unroll
    for (int i = 0; i < 8; i++)
        #pragma unroll
        for (int j = 0; j < 8; j++) acc[i][j] = 0.f;

    for (int k0 = 0; k0 < K; k0 += 16){
        float4 a0 = *(const float4*)(Ap + k0);
        float4 a1 = *(const float4*)(Ap + k0 + 4);
        float4 b0 = *(const float4*)(Bp + (size_t)k0*Nn);
        float4 b1 = *(const float4*)(Bp + (size_t)(k0+8)*Nn);
        __syncthreads();
        As[aq+0][arow] = a0.x; As[aq+1][arow] = a0.y; As[aq+2][arow] = a0.z; As[aq+3][arow] = a0.w;
        As[aq+4][arow] = a1.x; As[aq+5][arow] = a1.y; As[aq+6][arow] = a1.z; As[aq+7][arow] = a1.w;
        *(float4*)&Bs[brow][bcol]   = b0;
        *(float4*)&Bs[brow+8][bcol] = b1;
        __syncthreads();
        #pragma unroll
        for (int k = 0; k < 16; k++){
            float av[8], bv[8];
            *(float4*)(av)   = *(const float4*)&As[k][ty*8];
            *(float4*)(av+4) = *(const float4*)&As[k][ty*8+4];
            *(float4*)(bv)   = *(const float4*)&Bs[k][tx*8];
            *(float4*)(bv+4) = *(const float4*)&Bs[k][tx*8+4];
            #pragma unroll
            for (int i = 0; i < 8; i++)
                #pragma unroll
                for (int j = 0; j < 8; j++)
                    acc[i][j] = fmaf(av[i], bv[j], acc[i][j]);
        }
    }
    #pragma unroll
    for (int i = 0; i < 8; i++){
        size_t r = (size_t)(bm*128 + ty*8 + i)*Nn + bn*128 + tx*8;
        #pragma unroll
        for (int j = 0; j < 8; j++){
            float v = acc[i][j];
            if (BIAS) v += bias[bn*128 + tx*8 + j];
            if (RELU) v = (v > 0.f) ? v : 0.f;
            C[r + j] = v;
        }
    }
}

// ---------------- pad / gather / combine ----------------
__global__ void k_pad(const int* __restrict__ x, const float* __restrict__ tab_r,
                      float* __restrict__ out_graph){
    int idx = blockIdx.x*256 + threadIdx.x;           // 16,777,216 elems
    int row = idx >> 7, c = idx & 127;
    int b = row >> 9, p = row & 511;
    float og = 0.f, orr = 0.f;
    if (p < LL){
        int node = b*LL + p;
        og  = g_h3[node*128 + c];
        orr = 0.5f * (tab_r[x[node]*128 + c] + g_emb2[node*128 + c]);
    }
    out_graph[idx] = og;
    g_outr[idx]    = orr;
}
__global__ void k_mask(float* __restrict__ m1, float* __restrict__ m2){
    int idx = blockIdx.x*256 + threadIdx.x;           // 131072
    float v = ((idx & 511) < LL) ? 1.f : 0.f;
    m1[idx] = v; m2[idx] = v;
}

// ---------------- merged 15-tap conv, output [b][t][oc] ----------------
__global__ void __launch_bounds__(256) k_conv(){
    extern __shared__ float sm[];
    float* xs = sm;                 // [32][144]
    float* ws = sm + 32*144;        // [32][15][64]
    int b = blockIdx.y, t0 = blockIdx.x * 128;
    int tid = threadIdx.x;
    int oc0 = (tid & 15) * 4;
    int tb = (tid >> 4) * 8;
    float acc[4][8];
    #pragma unroll
    for (int o = 0; o < 4; o++)
        #pragma unroll
        for (int t = 0; t < 8; t++) acc[o][t] = 0.f;

    for (int icc = 0; icc < 128; icc += 32){
        __syncthreads();
        for (int i = tid; i < 142*32; i += 256){
            int p = i >> 5, ic = i & 31;
            int tg = t0 - 7 + p;
            float v = (tg >= 0 && tg < PADL) ? g_outr[((size_t)b*PADL + tg)*128 + icc + ic] : 0.f;
            xs[ic*144 + p] = v;
        }
        const float4* wsrc = (const float4*)(g_weff + icc*960);
        for (int i = tid; i < 32*960/4; i += 256) ((float4*)ws)[i] = wsrc[i];
        __syncthreads();
        for (int icl = 0; icl < 32; icl++){
            float xrv[22];
            #pragma unroll
            for (int u = 0; u < 22; u++) xrv[u] = xs[icl*144 + tb + u];
            const float* wrow = ws + icl*960 + oc0;
            #pragma unroll
            for (int j = 0; j < 15; j++){
                float4 wv = *(const float4*)(wrow + j*64);
                #pragma unroll
                for (int t = 0; t < 8; t++){
                    float xv = xrv[t + j];
                    acc[0][t] = fmaf(wv.x, xv, acc[0][t]);
                    acc[1][t] = fmaf(wv.y, xv, acc[1][t]);
                    acc[2][t] = fmaf(wv.z, xv, acc[2][t]);
                    acc[3][t] = fmaf(wv.w, xv, acc[3][t]);
                }
            }
        }
    }
    #pragma unroll
    for (int t = 0; t < 8; t++){
        float* yp = g_y + ((size_t)b*PADL + t0 + tb + t)*64 + oc0;
        #pragma unroll
        for (int o = 0; o < 4; o++) yp[o] = acc[o][t] + g_beff[oc0 + o];
    }
}

// ---------------- pools ----------------
__global__ void k_pool_graph(float* __restrict__ out){
    int b = blockIdx.x, c = threadIdx.x;
    float s = 0.f;
    for (int p = 0; p < LL; p++) s += g_h3[(b*LL + p)*128 + c];
    out[b*128 + c] = s * (1.f / (float)LL);
}
__global__ void k_pool_seq(const float* __restrict__ ocnn, float* __restrict__ out){
    int b = blockIdx.x, c = threadIdx.x;
    float s = 0.f;
    for (int p = 0; p < LL; p++) s += ocnn[((size_t)b*PADL + p)*128 + c];
    out[b*128 + c] = s * (1.f / (float)PADL);
}

// ---------------- launch ----------------
#define SYMADDR(var, sym) float* var; { void* _p; cudaGetSymbolAddress(&_p, sym); var = (float*)_p; }

extern "C" void kernel_launch(void* const* d_in, const int* in_sizes, int n_in,
                              void* d_out, int out_size){
    const int*   x     = (const int*)d_in[0];
    const int*   ei    = (const int*)d_in[1];
    const int*   esrc  = ei;
    const int*   edst  = ei + EE;
    const float* emb   = (const float*)d_in[2];
    const float* tab_r = (const float*)d_in[5];
    const float* tab_g = (const float*)d_in[6];
    const float* W1    = (const float*)d_in[7];
    const float* a1s   = (const float*)d_in[8];
    const float* a1d   = (const float*)d_in[9];
    const float* b1    = (const float*)d_in[10];
    const float* W2    = (const float*)d_in[11];
    const float* a2s   = (const float*)d_in[12];
    const float* a2d   = (const float*)d_in[13];
    const float* b2    = (const float*)d_in[14];
    const float* W3    = (const float*)d_in[15];
    const float* a3s   = (const float*)d_in[16];
    const float* a3d   = (const float*)d_in[17];
    const float* b3    = (const float*)d_in[18];
    const float* le_W  = (const float*)d_in[19];
    const float* le_b  = (const float*)d_in[20];
    const float* cw1   = (const float*)d_in[21];
    const float* cb1   = (const float*)d_in[22];
    const float* cw2   = (const float*)d_in[23];
    const float* cb2   = (const float*)d_in[24];
    const float* cw3   = (const float*)d_in[25];
    const float* cb3   = (const float*)d_in[26];
    const float* l1W   = (const float*)d_in[27];
    const float* l1b   = (const float*)d_in[28];
    const float* l2W   = (const float*)d_in[29];
    const float* l2b   = (const float*)d_in[30];
    float* out = (float*)d_out;

    SYMADDR(p_h1, g_h1); SYMADDR(p_hpre2, g_hpre2); SYMADDR(p_h2, g_h2);
    SYMADDR(p_hpre3, g_hpre3); SYMADDR(p_h3, g_h3); SYMADDR(p_emb2, g_emb2);
    SYMADDR(p_y, g_y); SYMADDR(p_t1, g_t1); SYMADDR(p_tabh1, g_tabh1);
    SYMADDR(p_asn1, g_asn1); SYMADDR(p_adn1, g_adn1);
    SYMADDR(p_asn2, g_asn2); SYMADDR(p_adn2, g_adn2);
    SYMADDR(p_asn3, g_asn3); SYMADDR(p_adn3, g_adn3);
    void* p_off_v; cudaGetSymbolAddress(&p_off_v, g_off); int* p_off = (int*)p_off_v;
    void* p_csr_v; cudaGetSymbolAddress(&p_csr_v, g_csr); int* p_csr = (int*)p_csr_v;
    void* p_cnt_v; cudaGetSymbolAddress(&p_cnt_v, g_cnt); int* p_cnt = (int*)p_cnt_v;

    cudaFuncSetAttribute(k_conv, cudaFuncAttributeMaxDynamicSharedMemorySize, 141312);

    // tables
    k_tab_h1<<<24, 256>>>(tab_g, W1);
    k_tab_attn<<<1, 1024>>>(a1s, a1d);
    k_asn1<<<1600, 256>>>(x);
    k_weff<<<480, 256>>>(cw1, cb1, cw2, cb2, cw3, cb3);

    // CSR
    cudaMemsetAsync(p_cnt, 0, NN*sizeof(int));
    k_count<<<EE/256, 256>>>(edst);
    k_scan1<<<100, 1024>>>();
    k_scan2<<<1, 32>>>();
    k_scan3<<<100, 1024>>>();
    k_fill<<<EE/256, 256>>>(esrc, edst);

    // GAT layer 1 (h matrix = 6-row table, remap through node type)
    k_gat_agg<4,256><<<NN/8, 256>>>(p_tabh1, x, p_asn1, p_adn1, b1, p_h1, p_off, p_csr);

    // GAT layer 2
    k_sgemm<false,false><<<dim3(8, NN/128), 256>>>(p_h1, W2, nullptr, p_hpre2, NN, 1024, 256);
    k_dots<4,256><<<NN*4/8, 256>>>(p_hpre2, a2s, a2d, p_asn2, p_adn2);
    k_gat_agg<4,256><<<NN/8, 256>>>(p_hpre2, nullptr, p_asn2, p_adn2, b2, p_h2, p_off, p_csr);

    // GAT layer 3
    k_sgemm<false,false><<<dim3(1, NN/128), 256>>>(p_h2, W3, nullptr, p_hpre3, NN, 128, 256);
    k_dots<1,128><<<NN/8, 256>>>(p_hpre3, a3s, a3d, p_asn3, p_adn3);
    k_gat_agg<1,128><<<NN/8, 256>>>(p_hpre3, nullptr, p_asn3, p_adn3, b3, p_h3, p_off, p_csr);

    // graph pool
    k_pool_graph<<<BB, 128>>>(out + OFF_EMBGR);

    // line embedding
    k_sgemm<true,true><<<dim3(1, NN/128), 256>>>(emb, le_W, le_b, p_emb2, NN, 128, 640);

    // pad / gather / combine + masks
    k_pad<<<65536, 256>>>(x, tab_r, out + OFF_GRAPH);
    k_mask<<<512, 256>>>(out + OFF_MASK1, out + OFF_MASK2);

    // merged conv
    k_conv<<<dim3(4, BB), 256, 141312>>>();

    // MLP head
    k_sgemm<true,true><<<dim3(4, (BB*PADL)/128), 256>>>(p_y, l1W, l1b, p_t1, BB*PADL, 512, 64);
    k_sgemm<true,false><<<dim3(1, (BB*PADL)/128), 256>>>(p_t1, l2W, l2b, out + OFF_SEQCNN, BB*PADL, 128, 512);

    // seq pool
    k_pool_seq<<<BB, 128>>>(out + OFF_SEQCNN, out + OFF_EMBSEQ);
}

// round 3
// speedup vs baseline: 1.0032x; 1.0032x over previous
#include <cuda_runtime.h>
#include <cstdint>

#define NN   102400
#define BB   256
#define LL   400
#define EE   819200
#define PADL 512

static const size_t OFF_SEQCNN = 0;
static const size_t OFF_GRAPH  = 16777216;
static const size_t OFF_MASK1  = 33554432;
static const size_t OFF_MASK2  = 33685504;
static const size_t OFF_EMBSEQ = 33816576;
static const size_t OFF_EMBGR  = 33849344;

// ---------------- scratch (device globals: no allocation allowed) ----------------
__device__ float g_h1[NN*256];
__device__ float g_hpre2[104857600];      // N x 1024
__device__ float g_h2[NN*256];
__device__ float g_hpre3[NN*128];
__device__ float g_h3[NN*128];
__device__ float g_emb2[NN*128];
__device__ float g_outr[BB*PADL*128];
__device__ float g_y[BB*PADL*64];
__device__ float g_t1[67108864];          // (B*512) x 512
__device__ float g_asn1[NN*4], g_adn1[NN*4];
__device__ float g_asn2[NN*4], g_adn2[NN*4];
__device__ float g_asn3[NN],   g_adn3[NN];
__device__ float g_tabh1[6*1024], g_tabas1[24], g_tabad1[24];
__device__ float g_weff[128*15*64], g_beff[64];
__device__ int g_cnt[NN], g_incl[NN], g_bsum[128], g_off[NN+1], g_cur[NN], g_csr[EE];

// ---------------- small table kernels ----------------
__global__ void k_tab_h1(const float* __restrict__ tabg, const float* __restrict__ W1){
    int idx = blockIdx.x*256 + threadIdx.x;           // < 6144
    int v = idx >> 10, col = idx & 1023;
    float s = 0.f;
    for (int k = 0; k < 128; k++) s += tabg[v*128+k] * W1[k*1024+col];
    g_tabh1[idx] = s;
}

__global__ void k_tab_attn(const float* __restrict__ a1s, const float* __restrict__ a1d){
    int w = threadIdx.x >> 5, lane = threadIdx.x & 31;
    if (w >= 24) return;
    int v = w >> 2, h = w & 3;
    float s = 0.f, d = 0.f;
    for (int c = lane; c < 256; c += 32){
        float hv = g_tabh1[v*1024 + h*256 + c];
        s += hv * a1s[h*256+c];
        d += hv * a1d[h*256+c];
    }
    for (int o = 16; o > 0; o >>= 1){
        s += __shfl_xor_sync(0xffffffffu, s, o);
        d += __shfl_xor_sync(0xffffffffu, d, o);
    }
    if (lane == 0){ g_tabas1[v*4+h] = s; g_tabad1[v*4+h] = d; }
}

__global__ void k_asn1(const int* __restrict__ x){
    int i = blockIdx.x*256 + threadIdx.x;
    if (i >= NN*4) return;
    int node = i >> 2, h = i & 3;
    int xi = x[node];
    g_asn1[i] = g_tabas1[xi*4+h];
    g_adn1[i] = g_tabad1[xi*4+h];
}

__global__ void k_weff(const float* __restrict__ cw1, const float* __restrict__ cb1,
                       const float* __restrict__ cw2, const float* __restrict__ cb2,
                       const float* __restrict__ cw3, const float* __restrict__ cb3){
    int idx = blockIdx.x*256 + threadIdx.x;
    if (idx >= 128*15*64) return;
    int ic = idx / 960, rem = idx % 960, j = rem / 64, oc = rem % 64;
    float v = cw3[(oc*128+ic)*15 + j];
    if (j >= 2 && j < 13) v += cw2[(oc*128+ic)*11 + (j-2)];
    if (j >= 4 && j < 11) v += cw1[(oc*128+ic)*7  + (j-4)];
    g_weff[idx] = v * (1.f/3.f);
    if (idx < 64) g_beff[idx] = (cb1[idx] + cb2[idx] + cb3[idx]) * (1.f/3.f);
}

// ---------------- CSR build ----------------
__global__ void k_count(const int* __restrict__ dst){
    int e = blockIdx.x*256 + threadIdx.x;
    if (e < EE) atomicAdd(&g_cnt[dst[e]], 1);
}
__global__ void k_scan1(){
    __shared__ int sh[1024];
    int tid = threadIdx.x;
    int i = blockIdx.x*1024 + tid;
    sh[tid] = g_cnt[i];
    __syncthreads();
    for (int ofs = 1; ofs < 1024; ofs <<= 1){
        int t = (tid >= ofs) ? sh[tid-ofs] : 0;
        __syncthreads();
        sh[tid] += t;
        __syncthreads();
    }
    g_incl[i] = sh[tid];
    if (tid == 1023) g_bsum[blockIdx.x] = sh[1023];
}
__global__ void k_scan2(){
    if (threadIdx.x == 0){
        int acc = 0;
        for (int i = 0; i < 100; i++){ int v = g_bsum[i]; g_bsum[i] = acc; acc += v; }
    }
}
__global__ void k_scan3(){
    int i = blockIdx.x*1024 + threadIdx.x;
    int ex = g_incl[i] - g_cnt[i] + g_bsum[blockIdx.x];
    g_off[i] = ex;
    g_cur[i] = ex;
    if (i == 0) g_off[NN] = EE;
}
__global__ void k_fill(const int* __restrict__ src, const int* __restrict__ dst){
    int e = blockIdx.x*256 + threadIdx.x;
    if (e >= EE) return;
    int d = dst[e];
    int p = atomicAdd(&g_cur[d], 1);
    g_csr[p] = src[e];
}

// ---------------- GAT aggregation: one warp per destination node ----------------
template<int H, int CH>
__global__ void k_gat_agg(const float* __restrict__ hmat, const int* __restrict__ remap,
                          const float* __restrict__ asn, const float* __restrict__ adn,
                          const float* __restrict__ bias, float* __restrict__ outp,
                          const int* __restrict__ off, const int* __restrict__ csr){
    const int P = CH/32;
    __shared__ int   s_src[8][128];
    __shared__ float s_al[8][128*H];
    int w = threadIdx.x >> 5, lane = threadIdx.x & 31;
    int node = blockIdx.x*8 + w;
    if (node >= NN) return;

    float ad[H], m[H], den[H], eself[H];
    #pragma unroll
    for (int h = 0; h < H; h++) ad[h] = adn[node*H+h];
    #pragma unroll
    for (int h = 0; h < H; h++){
        float v = asn[node*H+h] + ad[h];
        eself[h] = (v > 0.f) ? v : 0.2f*v;
        m[h] = eself[h];
    }
    int s0 = off[node], s1 = off[node+1];

    // pass 1: max
    for (int e = s0 + lane; e < s1; e += 32){
        int s = csr[e];
        #pragma unroll
        for (int h = 0; h < H; h++){
            float v = asn[s*H+h] + ad[h];
            v = (v > 0.f) ? v : 0.2f*v;
            m[h] = fmaxf(m[h], v);
        }
    }
    #pragma unroll
    for (int h = 0; h < H; h++)
        for (int o = 16; o > 0; o >>= 1) m[h] = fmaxf(m[h], __shfl_xor_sync(0xffffffffu, m[h], o));

    // pass 2: denom
    #pragma unroll
    for (int h = 0; h < H; h++) den[h] = 0.f;
    for (int e = s0 + lane; e < s1; e += 32){
        int s = csr[e];
        #pragma unroll
        for (int h = 0; h < H; h++){
            float v = asn[s*H+h] + ad[h];
            v = (v > 0.f) ? v : 0.2f*v;
            den[h] += __expf(v - m[h]);
        }
    }
    #pragma unroll
    for (int h = 0; h < H; h++){
        for (int o = 16; o > 0; o >>= 1) den[h] += __shfl_xor_sync(0xffffffffu, den[h], o);
        den[h] += __expf(eself[h] - m[h]);
    }
    float rden[H];
    #pragma unroll
    for (int h = 0; h < H; h++) rden[h] = 1.f / den[h];

    float acc[H][P];
    #pragma unroll
    for (int h = 0; h < H; h++)
        #pragma unroll
        for (int p = 0; p < P; p++) acc[h][p] = 0.f;

    // self loop
    {
        int row = remap ? remap[node] : node;
        const float* hp = hmat + (size_t)row*(H*CH);
        #pragma unroll
        for (int h = 0; h < H; h++){
            float a = __expf(eself[h] - m[h]) * rden[h];
            #pragma unroll
            for (int p = 0; p < P; p++) acc[h][p] += a * hp[h*CH + p*32 + lane];
        }
    }

    // pass 3: chunked weighted accumulate
    for (int base = s0; base < s1; base += 128){
        int cn = min(128, s1 - base);
        for (int e = lane; e < cn; e += 32){
            int s = csr[base + e];
            #pragma unroll
            for (int h = 0; h < H; h++){
                float v = asn[s*H+h] + ad[h];
                v = (v > 0.f) ? v : 0.2f*v;
                s_al[w][e*H+h] = __expf(v - m[h]) * rden[h];
            }
            s_src[w][e] = remap ? remap[s] : s;
        }
        __syncwarp();
        for (int e = 0; e < cn; e++){
            int row = s_src[w][e];
            const float* hp = hmat + (size_t)row*(H*CH);
            #pragma unroll
            for (int h = 0; h < H; h++){
                float a = s_al[w][e*H+h];
                #pragma unroll
                for (int p = 0; p < P; p++) acc[h][p] += a * hp[h*CH + p*32 + lane];
            }
        }
        __syncwarp();
    }

    const float invH = 1.f / (float)H;
    #pragma unroll
    for (int p = 0; p < P; p++){
        float v = 0.f;
        #pragma unroll
        for (int h = 0; h < H; h++) v += acc[h][p];
        v = v*invH + bias[p*32 + lane];
        outp[(size_t)node*CH + p*32 + lane] = (v > 0.f) ? v : 0.f;
    }
}

// ---------------- per-node attention dots (layers 2,3) ----------------
template<int H, int CH>
__global__ void k_dots(const float* __restrict__ hpre, const float* __restrict__ aw_s,
                       const float* __restrict__ aw_d, float* __restrict__ asn, float* __restrict__ adn){
    int gw = blockIdx.x*8 + (threadIdx.x >> 5);
    int lane = threadIdx.x & 31;
    if (gw >= NN*H) return;
    int node = gw / H, h = gw - node*H;
    const float* hp = hpre + (size_t)node*(H*CH) + h*CH;
    float s = 0.f, d = 0.f;
    for (int c = lane; c < CH; c += 32){
        float v = hp[c];
        s += v * aw_s[h*CH+c];
        d += v * aw_d[h*CH+c];
    }
    for (int o = 16; o > 0; o >>= 1){
        s += __shfl_xor_sync(0xffffffffu, s, o);
        d += __shfl_xor_sync(0xffffffffu, d, o);
    }
    if (lane == 0){ asn[gw] = s; adn[gw] = d; }
}

// ---------------- SGEMM: C = A(MxK) * B(KxN) [+bias][relu], tiles 128x128x16 ----------------
template<bool BIAS, bool RELU>
__global__ void __launch_bounds__(256) k_sgemm(const float* __restrict__ A, const float* __restrict__ B,
                                               const float* __restrict__ bias, float* __restrict__ C,
                                               int M, int Nn, int K){
    __shared__ float As[16][128];
    __shared__ float Bs[16][128];
    int tid = threadIdx.x;
    int bm = blockIdx.y, bn = blockIdx.x;
    int ty = tid >> 4, tx = tid & 15;
    int arow = tid >> 1, aq = (tid & 1) * 8;
    int brow = tid >> 5, bcol = (tid & 31) * 4;
    const float* Ap = A + (size_t)(bm*128 + arow)*K + aq;
    const float* Bp = B + (size_t)brow*Nn + bn*128 + bcol;
    float acc[8][8];
    #pragma unroll
    for (int i = 0; i < 8; i++)
        #pragma unroll
        for (int j = 0; j < 8; j++) acc[i][j] = 0.f;

    for (int k0 = 0; k0 < K; k0 += 16){
        float4 a0 = *(const float4*)(Ap + k0);
        float4 a1 = *(const float4*)(Ap + k0 + 4);
        float4 b0 = *(const float4*)(Bp + (size_t)k0*Nn);
        float4 b1 = *(const float4*)(Bp + (size_t)(k0+8)*Nn);
        __syncthreads();
        As[aq+0][arow] = a0.x; As[aq+1][arow] = a0.y; As[aq+2][arow] = a0.z; As[aq+3][arow] = a0.w;
        As[aq+4][arow] = a1.x; As[aq+5][arow] = a1.y; As[aq+6][arow] = a1.z; As[aq+7][arow] = a1.w;
        *(float4*)&Bs[brow][bcol]   = b0;
        *(float4*)&Bs[brow+8][bcol] = b1;
        __syncthreads();
        #pragma unroll
        for (int k = 0; k < 16; k++){
            float av[8], bv[8];
            *(float4*)(av)   = *(const float4*)&As[k][ty*8];
            *(float4*)(av+4) = *(const float4*)&As[k][ty*8+4];
            *(float4*)(bv)   = *(const float4*)&Bs[k][tx*8];
            *(float4*)(bv+4) = *(const float4*)&Bs[k][tx*8+4];
            #pragma unroll
            for (int i = 0; i < 8; i++)
                #pragma unroll
                for (int j = 0; j < 8; j++)
                    acc[i][j] = fmaf(av[i], bv[j], acc[i][j]);
        }
    }
    #pragma unroll
    for (int i = 0; i < 8; i++){
        size_t r = (size_t)(bm*128 + ty*8 + i)*Nn + bn*128 + tx*8;
        #pragma unroll
        for (int j = 0; j < 8; j++){
            float v = acc[i][j];
            if (BIAS) v += bias[bn*128 + tx*8 + j];
            if (RELU) v = (v > 0.f) ? v : 0.f;
            C[r + j] = v;
        }
    }
}

// ---------------- pad / gather / combine ----------------
__global__ void k_pad(const int* __restrict__ x, const float* __restrict__ tab_r,
                      float* __restrict__ out_graph){
    int idx = blockIdx.x*256 + threadIdx.x;           // 16,777,216 elems
    int row = idx >> 7, c = idx & 127;
    int b = row >> 9, p = row & 511;
    float og = 0.f, orr = 0.f;
    if (p < LL){
        int node = b*LL + p;
        og  = g_h3[node*128 + c];
        orr = 0.5f * (tab_r[x[node]*128 + c] + g_emb2[node*128 + c]);
    }
    out_graph[idx] = og;
    g_outr[idx]    = orr;
}
__global__ void k_mask(float* __restrict__ m1, float* __restrict__ m2){
    int idx = blockIdx.x*256 + threadIdx.x;           // 131072
    float v = ((idx & 511) < LL) ? 1.f : 0.f;
    m1[idx] = v; m2[idx] = v;
}

// ---------------- merged 15-tap conv, output [b][t][oc] ----------------
__global__ void __launch_bounds__(256) k_conv(){
    extern __shared__ float sm[];
    float* xs = sm;                 // [32][144]
    float* ws = sm + 32*144;        // [32][15][64]
    int b = blockIdx.y, t0 = blockIdx.x * 128;
    int tid = threadIdx.x;
    int oc0 = (tid & 15) * 4;
    int tb = (tid >> 4) * 8;
    float acc[4][8];
    #pragma unroll
    for (int o = 0; o < 4; o++)
        #pragma unroll
        for (int t = 0; t < 8; t++) acc[o][t] = 0.f;

    for (int icc = 0; icc < 128; icc += 32){
        __syncthreads();
        for (int i = tid; i < 142*32; i += 256){
            int p = i >> 5, ic = i & 31;
            int tg = t0 - 7 + p;
            float v = (tg >= 0 && tg < PADL) ? g_outr[((size_t)b*PADL + tg)*128 + icc + ic] : 0.f;
            xs[ic*144 + p] = v;
        }
        const float4* wsrc = (const float4*)(g_weff + icc*960);
        for (int i = tid; i < 32*960/4; i += 256) ((float4*)ws)[i] = wsrc[i];
        __syncthreads();
        for (int icl = 0; icl < 32; icl++){
            float xrv[22];
            #pragma unroll
            for (int u = 0; u < 22; u++) xrv[u] = xs[icl*144 + tb + u];
            const float* wrow = ws + icl*960 + oc0;
            #pragma unroll
            for (int j = 0; j < 15; j++){
                float4 wv = *(const float4*)(wrow + j*64);
                #pragma unroll
                for (int t = 0; t < 8; t++){
                    float xv = xrv[t + j];
                    acc[0][t] = fmaf(wv.x, xv, acc[0][t]);
                    acc[1][t] = fmaf(wv.y, xv, acc[1][t]);
                    acc[2][t] = fmaf(wv.z, xv, acc[2][t]);
                    acc[3][t] = fmaf(wv.w, xv, acc[3][t]);
                }
            }
        }
    }
    #pragma unroll
    for (int t = 0; t < 8; t++){
        float* yp = g_y + ((size_t)b*PADL + t0 + tb + t)*64 + oc0;
        #pragma unroll
        for (int o = 0; o < 4; o++) yp[o] = acc[o][t] + g_beff[oc0 + o];
    }
}

// ---------------- pools ----------------
__global__ void k_pool_graph(float* __restrict__ out){
    int b = blockIdx.x, c = threadIdx.x;
    float s = 0.f;
    for (int p = 0; p < LL; p++) s += g_h3[(b*LL + p)*128 + c];
    out[b*128 + c] = s * (1.f / (float)LL);
}
__global__ void k_pool_seq(const float* __restrict__ ocnn, float* __restrict__ out){
    int b = blockIdx.x, c = threadIdx.x;
    float s = 0.f;
    for (int p = 0; p < LL; p++) s += ocnn[((size_t)b*PADL + p)*128 + c];
    out[b*128 + c] = s * (1.f / (float)PADL);
}

// ---------------- launch ----------------
#define SYMADDR(var, sym) float* var; { void* _p; cudaGetSymbolAddress(&_p, sym); var = (float*)_p; }

extern "C" void kernel_launch(void* const* d_in, const int* in_sizes, int n_in,
                              void* d_out, int out_size){
    const int*   x     = (const int*)d_in[0];
    const int*   ei    = (const int*)d_in[1];
    const int*   esrc  = ei;
    const int*   edst  = ei + EE;
    const float* emb   = (const float*)d_in[2];
    const float* tab_r = (const float*)d_in[5];
    const float* tab_g = (const float*)d_in[6];
    const float* W1    = (const float*)d_in[7];
    const float* a1s   = (const float*)d_in[8];
    const float* a1d   = (const float*)d_in[9];
    const float* b1    = (const float*)d_in[10];
    const float* W2    = (const float*)d_in[11];
    const float* a2s   = (const float*)d_in[12];
    const float* a2d   = (const float*)d_in[13];
    const float* b2    = (const float*)d_in[14];
    const float* W3    = (const float*)d_in[15];
    const float* a3s   = (const float*)d_in[16];
    const float* a3d   = (const float*)d_in[17];
    const float* b3    = (const float*)d_in[18];
    const float* le_W  = (const float*)d_in[19];
    const float* le_b  = (const float*)d_in[20];
    const float* cw1   = (const float*)d_in[21];
    const float* cb1   = (const float*)d_in[22];
    const float* cw2   = (const float*)d_in[23];
    const float* cb2   = (const float*)d_in[24];
    const float* cw3   = (const float*)d_in[25];
    const float* cb3   = (const float*)d_in[26];
    const float* l1W   = (const float*)d_in[27];
    const float* l1b   = (const float*)d_in[28];
    const float* l2W   = (const float*)d_in[29];
    const float* l2b   = (const float*)d_in[30];
    float* out = (float*)d_out;

    SYMADDR(p_h1, g_h1); SYMADDR(p_hpre2, g_hpre2); SYMADDR(p_h2, g_h2);
    SYMADDR(p_hpre3, g_hpre3); SYMADDR(p_h3, g_h3); SYMADDR(p_emb2, g_emb2);
    SYMADDR(p_y, g_y); SYMADDR(p_t1, g_t1); SYMADDR(p_tabh1, g_tabh1);
    SYMADDR(p_asn1, g_asn1); SYMADDR(p_adn1, g_adn1);
    SYMADDR(p_asn2, g_asn2); SYMADDR(p_adn2, g_adn2);
    SYMADDR(p_asn3, g_asn3); SYMADDR(p_adn3, g_adn3);
    void* p_off_v; cudaGetSymbolAddress(&p_off_v, g_off); int* p_off = (int*)p_off_v;
    void* p_csr_v; cudaGetSymbolAddress(&p_csr_v, g_csr); int* p_csr = (int*)p_csr_v;
    void* p_cnt_v; cudaGetSymbolAddress(&p_cnt_v, g_cnt); int* p_cnt = (int*)p_cnt_v;

    cudaFuncSetAttribute(k_conv, cudaFuncAttributeMaxDynamicSharedMemorySize, 141312);

    // tables
    k_tab_h1<<<24, 256>>>(tab_g, W1);
    k_tab_attn<<<1, 1024>>>(a1s, a1d);
    k_asn1<<<1600, 256>>>(x);
    k_weff<<<480, 256>>>(cw1, cb1, cw2, cb2, cw3, cb3);

    // CSR
    cudaMemsetAsync(p_cnt, 0, NN*sizeof(int));
    k_count<<<EE/256, 256>>>(edst);
    k_scan1<<<100, 1024>>>();
    k_scan2<<<1, 32>>>();
    k_scan3<<<100, 1024>>>();
    k_fill<<<EE/256, 256>>>(esrc, edst);

    // GAT layer 1 (h matrix = 6-row table, remap through node type)
    k_gat_agg<4,256><<<NN/8, 256>>>(p_tabh1, x, p_asn1, p_adn1, b1, p_h1, p_off, p_csr);

    // GAT layer 2
    k_sgemm<false,false><<<dim3(8, NN/128), 256>>>(p_h1, W2, nullptr, p_hpre2, NN, 1024, 256);
    k_dots<4,256><<<NN*4/8, 256>>>(p_hpre2, a2s, a2d, p_asn2, p_adn2);
    k_gat_agg<4,256><<<NN/8, 256>>>(p_hpre2, nullptr, p_asn2, p_adn2, b2, p_h2, p_off, p_csr);

    // GAT layer 3
    k_sgemm<false,false><<<dim3(1, NN/128), 256>>>(p_h2, W3, nullptr, p_hpre3, NN, 128, 256);
    k_dots<1,128><<<NN/8, 256>>>(p_hpre3, a3s, a3d, p_asn3, p_adn3);
    k_gat_agg<1,128><<<NN/8, 256>>>(p_hpre3, nullptr, p_asn3, p_adn3, b3, p_h3, p_off, p_csr);

    // graph pool
    k_pool_graph<<<BB, 128>>>(out + OFF_EMBGR);

    // line embedding
    k_sgemm<true,true><<<dim3(1, NN/128), 256>>>(emb, le_W, le_b, p_emb2, NN, 128, 640);

    // pad / gather / combine + masks
    k_pad<<<65536, 256>>>(x, tab_r, out + OFF_GRAPH);
    k_mask<<<512, 256>>>(out + OFF_MASK1, out + OFF_MASK2);

    // merged conv
    k_conv<<<dim3(4, BB), 256, 141312>>>();

    // MLP head
    k_sgemm<true,true><<<dim3(4, (BB*PADL)/128), 256>>>(p_y, l1W, l1b, p_t1, BB*PADL, 512, 64);
    k_sgemm<true,false><<<dim3(1, (BB*PADL)/128), 256>>>(p_t1, l2W, l2b, out + OFF_SEQCNN, BB*PADL, 128, 512);

    // seq pool
    k_pool_seq<<<BB, 128>>>(out + OFF_SEQCNN, out + OFF_EMBSEQ);
}

// round 5
// speedup vs baseline: 1.0055x; 1.0022x over previous
#include <cuda_runtime.h>
#include <cstdint>
#include <mma.h>
using namespace nvcuda;

#define NN   102400
#define BB   256
#define LL   400
#define EE   819200
#define PADL 512

static const size_t OFF_SEQCNN = 0;
static const size_t OFF_GRAPH  = 16777216;
static const size_t OFF_MASK1  = 33554432;
static const size_t OFF_MASK2  = 33685504;
static const size_t OFF_EMBSEQ = 33816576;
static const size_t OFF_EMBGR  = 33849344;

// ---------------- scratch (device globals: no allocation allowed) ----------------
__device__ float g_h1[NN*256];
__device__ float g_hpre2[104857600];      // N x 1024
__device__ float g_h2[NN*256];
__device__ float g_hpre3[NN*128];
__device__ float g_h3[NN*128];
__device__ float g_emb2[NN*128];
__device__ float g_outr[BB*PADL*128];
__device__ float g_y[BB*PADL*64];
__device__ float g_t1[67108864];          // (B*512) x 512
__device__ float g_asn1[NN*4], g_adn1[NN*4];
__device__ float g_asn2[NN*4], g_adn2[NN*4];
__device__ float g_asn3[NN],   g_adn3[NN];
__device__ float g_tabh1[6*1024], g_tabas1[24], g_tabad1[24];
__device__ float g_weff[128*15*64], g_beff[64];
__device__ int g_cnt[NN], g_incl[NN], g_bsum[128], g_off[NN+1], g_cur[NN], g_csr[EE];

// ---------------- small table kernels ----------------
__global__ void k_tab_h1(const float* __restrict__ tabg, const float* __restrict__ W1){
    int idx = blockIdx.x*256 + threadIdx.x;           // < 6144
    int v = idx >> 10, col = idx & 1023;
    float s = 0.f;
    for (int k = 0; k < 128; k++) s += tabg[v*128+k] * W1[k*1024+col];
    g_tabh1[idx] = s;
}

__global__ void k_tab_attn(const float* __restrict__ a1s, const float* __restrict__ a1d){
    int w = threadIdx.x >> 5, lane = threadIdx.x & 31;
    if (w >= 24) return;
    int v = w >> 2, h = w & 3;
    float s = 0.f, d = 0.f;
    for (int c = lane; c < 256; c += 32){
        float hv = g_tabh1[v*1024 + h*256 + c];
        s += hv * a1s[h*256+c];
        d += hv * a1d[h*256+c];
    }
    for (int o = 16; o > 0; o >>= 1){
        s += __shfl_xor_sync(0xffffffffu, s, o);
        d += __shfl_xor_sync(0xffffffffu, d, o);
    }
    if (lane == 0){ g_tabas1[v*4+h] = s; g_tabad1[v*4+h] = d; }
}

__global__ void k_asn1(const int* __restrict__ x){
    int i = blockIdx.x*256 + threadIdx.x;
    if (i >= NN*4) return;
    int node = i >> 2, h = i & 3;
    int xi = x[node];
    g_asn1[i] = g_tabas1[xi*4+h];
    g_adn1[i] = g_tabad1[xi*4+h];
}

__global__ void k_weff(const float* __restrict__ cw1, const float* __restrict__ cb1,
                       const float* __restrict__ cw2, const float* __restrict__ cb2,
                       const float* __restrict__ cw3, const float* __restrict__ cb3){
    int idx = blockIdx.x*256 + threadIdx.x;
    if (idx >= 128*15*64) return;
    int ic = idx / 960, rem = idx % 960, j = rem / 64, oc = rem % 64;
    float v = cw3[(oc*128+ic)*15 + j];
    if (j >= 2 && j < 13) v += cw2[(oc*128+ic)*11 + (j-2)];
    if (j >= 4 && j < 11) v += cw1[(oc*128+ic)*7  + (j-4)];
    g_weff[idx] = v * (1.f/3.f);
    if (idx < 64) g_beff[idx] = (cb1[idx] + cb2[idx] + cb3[idx]) * (1.f/3.f);
}

// ---------------- CSR build ----------------
__global__ void k_count(const int* __restrict__ dst){
    int e = blockIdx.x*256 + threadIdx.x;
    if (e < EE) atomicAdd(&g_cnt[dst[e]], 1);
}
__global__ void k_scan1(){
    __shared__ int sh[1024];
    int tid = threadIdx.x;
    int i = blockIdx.x*1024 + tid;
    sh[tid] = g_cnt[i];
    __syncthreads();
    for (int ofs = 1; ofs < 1024; ofs <<= 1){
        int t = (tid >= ofs) ? sh[tid-ofs] : 0;
        __syncthreads();
        sh[tid] += t;
        __syncthreads();
    }
    g_incl[i] = sh[tid];
    if (tid == 1023) g_bsum[blockIdx.x] = sh[1023];
}
__global__ void k_scan2(){
    if (threadIdx.x == 0){
        int acc = 0;
        for (int i = 0; i < 100; i++){ int v = g_bsum[i]; g_bsum[i] = acc; acc += v; }
    }
}
__global__ void k_scan3(){
    int i = blockIdx.x*1024 + threadIdx.x;
    int ex = g_incl[i] - g_cnt[i] + g_bsum[blockIdx.x];
    g_off[i] = ex;
    g_cur[i] = ex;
    if (i == 0) g_off[NN] = EE;
}
__global__ void k_fill(const int* __restrict__ src, const int* __restrict__ dst){
    int e = blockIdx.x*256 + threadIdx.x;
    if (e >= EE) return;
    int d = dst[e];
    int p = atomicAdd(&g_cur[d], 1);
    g_csr[p] = src[e];
}

// ---------------- GAT aggregation: one warp per destination node ----------------
template<int H, int CH>
__global__ void k_gat_agg(const float* __restrict__ hmat, const int* __restrict__ remap,
                          const float* __restrict__ asn, const float* __restrict__ adn,
                          const float* __restrict__ bias, float* __restrict__ outp,
                          const int* __restrict__ off, const int* __restrict__ csr){
    const int P = CH/32;
    __shared__ int   s_src[8][128];
    __shared__ float s_al[8][128*H];
    int w = threadIdx.x >> 5, lane = threadIdx.x & 31;
    int node = blockIdx.x*8 + w;
    if (node >= NN) return;

    float ad[H], m[H], den[H], eself[H];
    #pragma unroll
    for (int h = 0; h < H; h++) ad[h] = adn[node*H+h];
    #pragma unroll
    for (int h = 0; h < H; h++){
        float v = asn[node*H+h] + ad[h];
        eself[h] = (v > 0.f) ? v : 0.2f*v;
        m[h] = eself[h];
    }
    int s0 = off[node], s1 = off[node+1];

    // pass 1: max
    for (int e = s0 + lane; e < s1; e += 32){
        int s = csr[e];
        #pragma unroll
        for (int h = 0; h < H; h++){
            float v = asn[s*H+h] + ad[h];
            v = (v > 0.f) ? v : 0.2f*v;
            m[h] = fmaxf(m[h], v);
        }
    }
    #pragma unroll
    for (int h = 0; h < H; h++)
        for (int o = 16; o > 0; o >>= 1) m[h] = fmaxf(m[h], __shfl_xor_sync(0xffffffffu, m[h], o));

    // pass 2: denom
    #pragma unroll
    for (int h = 0; h < H; h++) den[h] = 0.f;
    for (int e = s0 + lane; e < s1; e += 32){
        int s = csr[e];
        #pragma unroll
        for (int h = 0; h < H; h++){
            float v = asn[s*H+h] + ad[h];
            v = (v > 0.f) ? v : 0.2f*v;
            den[h] += __expf(v - m[h]);
        }
    }
    #pragma unroll
    for (int h = 0; h < H; h++){
        for (int o = 16; o > 0; o >>= 1) den[h] += __shfl_xor_sync(0xffffffffu, den[h], o);
        den[h] += __expf(eself[h] - m[h]);
    }
    float rden[H];
    #pragma unroll
    for (int h = 0; h < H; h++) rden[h] = 1.f / den[h];

    float acc[H][P];
    #pragma unroll
    for (int h = 0; h < H; h++)
        #pragma unroll
        for (int p = 0; p < P; p++) acc[h][p] = 0.f;

    // self loop
    {
        int row = remap ? remap[node] : node;
        const float* hp = hmat + (size_t)row*(H*CH);
        #pragma unroll
        for (int h = 0; h < H; h++){
            float a = __expf(eself[h] - m[h]) * rden[h];
            #pragma unroll
            for (int p = 0; p < P; p++) acc[h][p] += a * hp[h*CH + p*32 + lane];
        }
    }

    // pass 3: chunked weighted accumulate
    for (int base = s0; base < s1; base += 128){
        int cn = min(128, s1 - base);
        for (int e = lane; e < cn; e += 32){
            int s = csr[base + e];
            #pragma unroll
            for (int h = 0; h < H; h++){
                float v = asn[s*H+h] + ad[h];
                v = (v > 0.f) ? v : 0.2f*v;
                s_al[w][e*H+h] = __expf(v - m[h]) * rden[h];
            }
            s_src[w][e] = remap ? remap[s] : s;
        }
        __syncwarp();
        for (int e = 0; e < cn; e++){
            int row = s_src[w][e];
            const float* hp = hmat + (size_t)row*(H*CH);
            #pragma unroll
            for (int h = 0; h < H; h++){
                float a = s_al[w][e*H+h];
                #pragma unroll
                for (int p = 0; p < P; p++) acc[h][p] += a * hp[h*CH + p*32 + lane];
            }
        }
        __syncwarp();
    }

    const float invH = 1.f / (float)H;
    #pragma unroll
    for (int p = 0; p < P; p++){
        float v = 0.f;
        #pragma unroll
        for (int h = 0; h < H; h++) v += acc[h][p];
        v = v*invH + bias[p*32 + lane];
        outp[(size_t)node*CH + p*32 + lane] = (v > 0.f) ? v : 0.f;
    }
}

// ---------------- per-node attention dots (layers 2,3) ----------------
template<int H, int CH>
__global__ void k_dots(const float* __restrict__ hpre, const float* __restrict__ aw_s,
                       const float* __restrict__ aw_d, float* __restrict__ asn, float* __restrict__ adn){
    int gw = blockIdx.x*8 + (threadIdx.x >> 5);
    int lane = threadIdx.x & 31;
    if (gw >= NN*H) return;
    int node = gw / H, h = gw - node*H;
    const float* hp = hpre + (size_t)node*(H*CH) + h*CH;
    float s = 0.f, d = 0.f;
    for (int c = lane; c < CH; c += 32){
        float v = hp[c];
        s += v * aw_s[h*CH+c];
        d += v * aw_d[h*CH+c];
    }
    for (int o = 16; o > 0; o >>= 1){
        s += __shfl_xor_sync(0xffffffffu, s, o);
        d += __shfl_xor_sync(0xffffffffu, d, o);
    }
    if (lane == 0){ asn[gw] = s; adn[gw] = d; }
}

// ---------------- TF32 tensor-core GEMM: C = A(MxK) * B(KxN) [+bias][relu] ----------------
// 128x128x16 tiles, 8 warps (2x4), 64x32 per warp via wmma m16n16k8.
#define AP 20
#define BP 132
template<bool BIAS, bool RELU>
__global__ void __launch_bounds__(256) k_mma(const float* __restrict__ A, const float* __restrict__ B,
                                             const float* __restrict__ bias, float* __restrict__ C,
                                             int M, int Nn, int K){
    __shared__ float As[2][128*AP];
    __shared__ float Bs[2][16*BP];
    int tid = threadIdx.x;
    int bm = blockIdx.y, bn = blockIdx.x;
    int warp = tid >> 5, lane = tid & 31;
    int wm = warp >> 2;        // 0..1 -> 64-row slab
    int wn = warp & 3;         // 0..3 -> 32-col slab

    wmma::fragment<wmma::accumulator,16,16,8,float> acc[4][2];
    #pragma unroll
    for (int i = 0; i < 4; i++)
        #pragma unroll
        for (int j = 0; j < 2; j++) wmma::fill_fragment(acc[i][j], 0.f);

    int arow = tid >> 1, aq = (tid & 1) * 8;
    int brow = tid >> 5, bcol = (tid & 31) * 4;
    const float* Ap_ = A + (size_t)(bm*128 + arow)*K + aq;
    const float* Bp_ = B + (size_t)brow*Nn + bn*128 + bcol;

    float4 ra0, ra1, rb0, rb1;
    ra0 = *(const float4*)(Ap_);
    ra1 = *(const float4*)(Ap_ + 4);
    rb0 = *(const float4*)(Bp_);
    rb1 = *(const float4*)(Bp_ + (size_t)8*Nn);

    {
        float* as = &As[0][arow*AP + aq];
        as[0]=ra0.x; as[1]=ra0.y; as[2]=ra0.z; as[3]=ra0.w;
        as[4]=ra1.x; as[5]=ra1.y; as[6]=ra1.z; as[7]=ra1.w;
        *(float4*)&Bs[0][brow*BP + bcol]     = rb0;
        *(float4*)&Bs[0][(brow+8)*BP + bcol] = rb1;
    }
    __syncthreads();

    int buf = 0;
    for (int k0 = 16;; k0 += 16){
        bool more = (k0 < K);
        if (more){
            ra0 = *(const float4*)(Ap_ + k0);
            ra1 = *(const float4*)(Ap_ + k0 + 4);
            rb0 = *(const float4*)(Bp_ + (size_t)k0*Nn);
            rb1 = *(const float4*)(Bp_ + (size_t)(k0+8)*Nn);
        }
        #pragma unroll
        for (int kk = 0; kk < 16; kk += 8){
            wmma::fragment<wmma::matrix_a,16,16,8,wmma::precision::tf32,wmma::row_major> af[4];
            wmma::fragment<wmma::matrix_b,16,16,8,wmma::precision::tf32,wmma::row_major> bf[2];
            #pragma unroll
            for (int i = 0; i < 4; i++){
                wmma::load_matrix_sync(af[i], &As[buf][(wm*64 + i*16)*AP + kk], AP);
                #pragma unroll
                for (int t = 0; t < af[i].num_elements; t++)
                    af[i].x[t] = wmma::__float_to_tf32(af[i].x[t]);
            }
            #pragma unroll
            for (int j = 0; j < 2; j++){
                wmma::load_matrix_sync(bf[j], &Bs[buf][kk*BP + wn*32 + j*16], BP);
                #pragma unroll
                for (int t = 0; t < bf[j].num_elements; t++)
                    bf[j].x[t] = wmma::__float_to_tf32(bf[j].x[t]);
            }
            #pragma unroll
            for (int i = 0; i < 4; i++)
                #pragma unroll
                for (int j = 0; j < 2; j++)
                    wmma::mma_sync(acc[i][j], af[i], bf[j], acc[i][j]);
        }
        if (!more) break;
        {
            float* as = &As[buf^1][arow*AP + aq];
            as[0]=ra0.x; as[1]=ra0.y; as[2]=ra0.z; as[3]=ra0.w;
            as[4]=ra1.x; as[5]=ra1.y; as[6]=ra1.z; as[7]=ra1.w;
            *(float4*)&Bs[buf^1][brow*BP + bcol]     = rb0;
            *(float4*)&Bs[buf^1][(brow+8)*BP + bcol] = rb1;
        }
        __syncthreads();
        buf ^= 1;
    }

    // epilogue: stage each 16x16 tile in smem (stride 20, multiple of 4 floats
    // as required by store_matrix_sync), apply bias/relu
    __syncthreads();
    float* stage = &As[0][warp*320];        // 16*20 per warp, 8*320=2560 fits As[0]
    int er = lane >> 1, ec0 = (lane & 1) * 8;
    #pragma unroll
    for (int i = 0; i < 4; i++){
        #pragma unroll
        for (int j = 0; j < 2; j++){
            wmma::store_matrix_sync(stage, acc[i][j], 20, wmma::mem_row_major);
            __syncwarp();
            int gr = bm*128 + wm*64 + i*16 + er;
            int gc = bn*128 + wn*32 + j*16 + ec0;
            float* cp = C + (size_t)gr*Nn + gc;
            #pragma unroll
            for (int t = 0; t < 8; t++){
                float v = stage[er*20 + ec0 + t];
                if (BIAS) v += bias[gc + t];
                if (RELU) v = (v > 0.f) ? v : 0.f;
                cp[t] = v;
            }
            __syncwarp();
        }
    }
}

// ---------------- pad / gather / combine ----------------
__global__ void k_pad(const int* __restrict__ x, const float* __restrict__ tab_r,
                      float* __restrict__ out_graph){
    int idx = blockIdx.x*256 + threadIdx.x;           // 16,777,216 elems
    int row = idx >> 7, c = idx & 127;
    int b = row >> 9, p = row & 511;
    float og = 0.f, orr = 0.f;
    if (p < LL){
        int node = b*LL + p;
        og  = g_h3[node*128 + c];
        orr = 0.5f * (tab_r[x[node]*128 + c] + g_emb2[node*128 + c]);
    }
    out_graph[idx] = og;
    g_outr[idx]    = orr;
}
__global__ void k_mask(float* __restrict__ m1, float* __restrict__ m2){
    int idx = blockIdx.x*256 + threadIdx.x;           // 131072
    float v = ((idx & 511) < LL) ? 1.f : 0.f;
    m1[idx] = v; m2[idx] = v;
}

// ---------------- merged 15-tap conv, output [b][t][oc] ----------------
__global__ void __launch_bounds__(256) k_conv(){
    extern __shared__ float sm[];
    float* xs = sm;                 // [32][144]
    float* ws = sm + 32*144;        // [32][15][64]
    int b = blockIdx.y, t0 = blockIdx.x * 128;
    int tid = threadIdx.x;
    int oc0 = (tid & 15) * 4;
    int tb = (tid >> 4) * 8;
    float acc[4][8];
    #pragma unroll
    for (int o = 0; o < 4; o++)
        #pragma unroll
        for (int t = 0; t < 8; t++) acc[o][t] = 0.f;

    for (int icc = 0; icc < 128; icc += 32){
        __syncthreads();
        for (int i = tid; i < 142*32; i += 256){
            int p = i >> 5, ic = i & 31;
            int tg = t0 - 7 + p;
            float v = (tg >= 0 && tg < PADL) ? g_outr[((size_t)b*PADL + tg)*128 + icc + ic] : 0.f;
            xs[ic*144 + p] = v;
        }
        const float4* wsrc = (const float4*)(g_weff + icc*960);
        for (int i = tid; i < 32*960/4; i += 256) ((float4*)ws)[i] = wsrc[i];
        __syncthreads();
        for (int icl = 0; icl < 32; icl++){
            float xrv[22];
            #pragma unroll
            for (int u = 0; u < 22; u++) xrv[u] = xs[icl*144 + tb + u];
            const float* wrow = ws + icl*960 + oc0;
            #pragma unroll
            for (int j = 0; j < 15; j++){
                float4 wv = *(const float4*)(wrow + j*64);
                #pragma unroll
                for (int t = 0; t < 8; t++){
                    float xv = xrv[t + j];
                    acc[0][t] = fmaf(wv.x, xv, acc[0][t]);
                    acc[1][t] = fmaf(wv.y, xv, acc[1][t]);
                    acc[2][t] = fmaf(wv.z, xv, acc[2][t]);
                    acc[3][t] = fmaf(wv.w, xv, acc[3][t]);
                }
            }
        }
    }
    #pragma unroll
    for (int t = 0; t < 8; t++){
        float* yp = g_y + ((size_t)b*PADL + t0 + tb + t)*64 + oc0;
        #pragma unroll
        for (int o = 0; o < 4; o++) yp[o] = acc[o][t] + g_beff[oc0 + o];
    }
}

// ---------------- pools ----------------
__global__ void k_pool_graph(float* __restrict__ out){
    int b = blockIdx.x, c = threadIdx.x;
    float s = 0.f;
    for (int p = 0; p < LL; p++) s += g_h3[(b*LL + p)*128 + c];
    out[b*128 + c] = s * (1.f / (float)LL);
}
__global__ void k_pool_seq(const float* __restrict__ ocnn, float* __restrict__ out){
    int b = blockIdx.x, c = threadIdx.x;
    float s = 0.f;
    for (int p = 0; p < LL; p++) s += ocnn[((size_t)b*PADL + p)*128 + c];
    out[b*128 + c] = s * (1.f / (float)PADL);
}

// ---------------- launch ----------------
#define SYMADDR(var, sym) float* var; { void* _p; cudaGetSymbolAddress(&_p, sym); var = (float*)_p; }

extern "C" void kernel_launch(void* const* d_in, const int* in_sizes, int n_in,
                              void* d_out, int out_size){
    const int*   x     = (const int*)d_in[0];
    const int*   ei    = (const int*)d_in[1];
    const int*   esrc  = ei;
    const int*   edst  = ei + EE;
    const float* emb   = (const float*)d_in[2];
    const float* tab_r = (const float*)d_in[5];
    const float* tab_g = (const float*)d_in[6];
    const float* W1    = (const float*)d_in[7];
    const float* a1s   = (const float*)d_in[8];
    const float* a1d   = (const float*)d_in[9];
    const float* b1    = (const float*)d_in[10];
    const float* W2    = (const float*)d_in[11];
    const float* a2s   = (const float*)d_in[12];
    const float* a2d   = (const float*)d_in[13];
    const float* b2    = (const float*)d_in[14];
    const float* W3    = (const float*)d_in[15];
    const float* a3s   = (const float*)d_in[16];
    const float* a3d   = (const float*)d_in[17];
    const float* b3    = (const float*)d_in[18];
    const float* le_W  = (const float*)d_in[19];
    const float* le_b  = (const float*)d_in[20];
    const float* cw1   = (const float*)d_in[21];
    const float* cb1   = (const float*)d_in[22];
    const float* cw2   = (const float*)d_in[23];
    const float* cb2   = (const float*)d_in[24];
    const float* cw3   = (const float*)d_in[25];
    const float* cb3   = (const float*)d_in[26];
    const float* l1W   = (const float*)d_in[27];
    const float* l1b   = (const float*)d_in[28];
    const float* l2W   = (const float*)d_in[29];
    const float* l2b   = (const float*)d_in[30];
    float* out = (float*)d_out;

    SYMADDR(p_h1, g_h1); SYMADDR(p_hpre2, g_hpre2); SYMADDR(p_h2, g_h2);
    SYMADDR(p_hpre3, g_hpre3); SYMADDR(p_h3, g_h3); SYMADDR(p_emb2, g_emb2);
    SYMADDR(p_y, g_y); SYMADDR(p_t1, g_t1); SYMADDR(p_tabh1, g_tabh1);
    SYMADDR(p_asn1, g_asn1); SYMADDR(p_adn1, g_adn1);
    SYMADDR(p_asn2, g_asn2); SYMADDR(p_adn2, g_adn2);
    SYMADDR(p_asn3, g_asn3); SYMADDR(p_adn3, g_adn3);
    void* p_off_v; cudaGetSymbolAddress(&p_off_v, g_off); int* p_off = (int*)p_off_v;
    void* p_csr_v; cudaGetSymbolAddress(&p_csr_v, g_csr); int* p_csr = (int*)p_csr_v;
    void* p_cnt_v; cudaGetSymbolAddress(&p_cnt_v, g_cnt); int* p_cnt = (int*)p_cnt_v;

    cudaFuncSetAttribute(k_conv, cudaFuncAttributeMaxDynamicSharedMemorySize, 141312);

    // tables
    k_tab_h1<<<24, 256>>>(tab_g, W1);
    k_tab_attn<<<1, 1024>>>(a1s, a1d);
    k_asn1<<<1600, 256>>>(x);
    k_weff<<<480, 256>>>(cw1, cb1, cw2, cb2, cw3, cb3);

    // CSR
    cudaMemsetAsync(p_cnt, 0, NN*sizeof(int));
    k_count<<<EE/256, 256>>>(edst);
    k_scan1<<<100, 1024>>>();
    k_scan2<<<1, 32>>>();
    k_scan3<<<100, 1024>>>();
    k_fill<<<EE/256, 256>>>(esrc, edst);

    // GAT layer 1 (h matrix = 6-row table, remap through node type)
    k_gat_agg<4,256><<<NN/8, 256>>>(p_tabh1, x, p_asn1, p_adn1, b1, p_h1, p_off, p_csr);

    // GAT layer 2
    k_mma<false,false><<<dim3(8, NN/128), 256>>>(p_h1, W2, nullptr, p_hpre2, NN, 1024, 256);
    k_dots<4,256><<<NN*4/8, 256>>>(p_hpre2, a2s, a2d, p_asn2, p_adn2);
    k_gat_agg<4,256><<<NN/8, 256>>>(p_hpre2, nullptr, p_asn2, p_adn2, b2, p_h2, p_off, p_csr);

    // GAT layer 3
    k_mma<false,false><<<dim3(1, NN/128), 256>>>(p_h2, W3, nullptr, p_hpre3, NN, 128, 256);
    k_dots<1,128><<<NN/8, 256>>>(p_hpre3, a3s, a3d, p_asn3, p_adn3);
    k_gat_agg<1,128><<<NN/8, 256>>>(p_hpre3, nullptr, p_asn3, p_adn3, b3, p_h3, p_off, p_csr);

    // graph pool
    k_pool_graph<<<BB, 128>>>(out + OFF_EMBGR);

    // line embedding
    k_mma<true,true><<<dim3(1, NN/128), 256>>>(emb, le_W, le_b, p_emb2, NN, 128, 640);

    // pad / gather / combine + masks
    k_pad<<<65536, 256>>>(x, tab_r, out + OFF_GRAPH);
    k_mask<<<512, 256>>>(out + OFF_MASK1, out + OFF_MASK2);

    // merged conv
    k_conv<<<dim3(4, BB), 256, 141312>>>();

    // MLP head
    k_mma<true,true><<<dim3(4, (BB*PADL)/128), 256>>>(p_y, l1W, l1b, p_t1, BB*PADL, 512, 64);
    k_mma<true,false><<<dim3(1, (BB*PADL)/128), 256>>>(p_t1, l2W, l2b, out + OFF_SEQCNN, BB*PADL, 128, 512);

    // seq pool
    k_pool_seq<<<BB, 128>>>(out + OFF_SEQCNN, out + OFF_EMBSEQ);
}